// round 3
// baseline (speedup 1.0000x reference)
#include <cuda_runtime.h>
#include <math.h>

#define D      256
#define NS     4096
#define NTOT   8192
#define TILE   128
#define TBLK   64                       // 8192 / 128 tiles per side
#define NPAIRS (TBLK*(TBLK+1)/2)        // 2080

__device__ float  g_sq[NTOT];
__device__ float  g_colsum[D];
__device__ double g_sumsq;
__device__ double g_acc;
__device__ float  g_cexp;

// ---------------------------------------------------------------- zero state
__global__ void k_zero() {
    int t = threadIdx.x;
    if (t < D) g_colsum[t] = 0.f;
    if (t == 0) { g_sumsq = 0.0; g_acc = 0.0; }
}

// ---------------------------------------------------------------- row stats
// 64 blocks x 256 threads; block b owns rows [b*128, b*128+128)
__global__ void k_stats(const float* __restrict__ src, const float* __restrict__ tgt) {
    int b    = blockIdx.x;
    int tid  = threadIdx.x;
    int lane = tid & 31;
    int warp = tid >> 5;
    __shared__ float wsum[8];

    // Phase A: per-row squared norms (one warp per row, 16 rows per warp)
    float ssq_local = 0.f;
    for (int r = warp; r < TILE; r += 8) {
        int i = b * TILE + r;
        const float* row = (i < NS) ? src + (size_t)i * D
                                    : tgt + (size_t)(i - NS) * D;
        float4 v0 = ((const float4*)row)[lane * 2];
        float4 v1 = ((const float4*)row)[lane * 2 + 1];
        float s = v0.x*v0.x + v0.y*v0.y + v0.z*v0.z + v0.w*v0.w
                + v1.x*v1.x + v1.y*v1.y + v1.z*v1.z + v1.w*v1.w;
        #pragma unroll
        for (int o = 16; o; o >>= 1) s += __shfl_xor_sync(0xffffffffu, s, o);
        if (lane == 0) { g_sq[i] = s; ssq_local += s; }
    }
    if (lane == 0) wsum[warp] = ssq_local;
    __syncthreads();
    if (tid == 0) {
        double bs = 0.0;
        #pragma unroll
        for (int w = 0; w < 8; ++w) bs += (double)wsum[w];
        atomicAdd(&g_sumsq, bs);
    }

    // Phase B: column partial sums (thread t owns column t; coalesced reads)
    float cs = 0.f;
    for (int r = 0; r < TILE; ++r) {
        int i = b * TILE + r;
        const float* row = (i < NS) ? src + (size_t)i * D
                                    : tgt + (size_t)(i - NS) * D;
        cs += row[tid];
    }
    atomicAdd(&g_colsum[tid], cs);
}

// ---------------------------------------------------------------- bandwidth
__global__ void k_prep() {
    __shared__ double sh[256];
    float c = g_colsum[threadIdx.x];
    sh[threadIdx.x] = (double)c * (double)c;
    __syncthreads();
    for (int o = 128; o; o >>= 1) {
        if (threadIdx.x < o) sh[threadIdx.x] += sh[threadIdx.x + o];
        __syncthreads();
    }
    if (threadIdx.x == 0) {
        double msq   = sh[0];
        double n     = (double)NTOT;
        double sumL2 = 2.0 * n * g_sumsq - 2.0 * msq;   // sum of clamped L2 (clamp effect ~1e-12)
        double bw0   = sumL2 / (n * n - n) / 4.0;       // / KERNEL_MUL^(KERNEL_NUM/2)=4
        // a = exp(-L2/(16*bw0)) = exp2(-g_cexp * L2)
        g_cexp = (float)(1.4426950408889634 / (bw0 * 16.0));
    }
}

// ---------------------------------------------------------------- main tiles
// 2080 blocks over (bi<=bj) 128x128 tile pairs; 256 threads; 8x8 per thread.
__global__ void __launch_bounds__(256, 2)
k_mmd(const float* __restrict__ src, const float* __restrict__ tgt) {
    __shared__ float As[2][16][132];
    __shared__ float Bs[2][16][132];
    __shared__ float wred[8];

    // --- map linear pair index -> (bi, bj), bi <= bj --------------------
    int idx = blockIdx.x;
    float tt = 2.f * TBLK + 1.f;
    int bi = (int)((tt - sqrtf(tt * tt - 8.f * (float)idx)) * 0.5f);
    if (bi < 0) bi = 0;
    if (bi > TBLK - 1) bi = TBLK - 1;
    while (bi > 0 && bi * TBLK - bi * (bi - 1) / 2 > idx) --bi;
    while ((bi + 1) * TBLK - (bi + 1) * bi / 2 <= idx) ++bi;
    int bj = bi + idx - (bi * TBLK - bi * (bi - 1) / 2);

    const float* Abase = (bi < 32) ? src + (size_t)bi * TILE * D
                                   : tgt + (size_t)(bi - 32) * TILE * D;
    const float* Bbase = (bj < 32) ? src + (size_t)bj * TILE * D
                                   : tgt + (size_t)(bj - 32) * TILE * D;

    int tid = threadIdx.x;
    int tx = tid & 15, ty = tid >> 4;
    int lane = tid & 31, warp = tid >> 5;

    float acc[8][8];
    #pragma unroll
    for (int r = 0; r < 8; ++r)
        #pragma unroll
        for (int c = 0; c < 8; ++c) acc[r][c] = 0.f;

    int lrow0 = tid >> 2;      // 0..63 ; rows lrow0 and lrow0+64
    int lquad = tid & 3;       // which float4 within the 16-wide k slab
    int kq    = lquad * 4;

    // preload k-slab 0
    #pragma unroll
    for (int it = 0; it < 2; ++it) {
        int row = lrow0 + it * 64;
        float4 a  = *(const float4*)(Abase + (size_t)row * D + kq);
        float4 bv = *(const float4*)(Bbase + (size_t)row * D + kq);
        As[0][kq+0][row] = a.x;  As[0][kq+1][row] = a.y;
        As[0][kq+2][row] = a.z;  As[0][kq+3][row] = a.w;
        Bs[0][kq+0][row] = bv.x; Bs[0][kq+1][row] = bv.y;
        Bs[0][kq+2][row] = bv.z; Bs[0][kq+3][row] = bv.w;
    }
    __syncthreads();

    #pragma unroll 1
    for (int t = 0; t < 16; ++t) {
        int cur = t & 1, nxt = cur ^ 1;
        float4 pa[2], pb[2];
        if (t < 15) {
            int k0 = (t + 1) * 16;
            #pragma unroll
            for (int it = 0; it < 2; ++it) {
                int row = lrow0 + it * 64;
                pa[it] = *(const float4*)(Abase + (size_t)row * D + k0 + kq);
                pb[it] = *(const float4*)(Bbase + (size_t)row * D + k0 + kq);
            }
        }
        #pragma unroll
        for (int k = 0; k < 16; ++k) {
            float4 a0 = *(const float4*)&As[cur][k][ty * 8];
            float4 a1 = *(const float4*)&As[cur][k][ty * 8 + 4];
            float4 b0 = *(const float4*)&Bs[cur][k][tx * 8];
            float4 b1 = *(const float4*)&Bs[cur][k][tx * 8 + 4];
            float ra[8] = {a0.x, a0.y, a0.z, a0.w, a1.x, a1.y, a1.z, a1.w};
            float rb[8] = {b0.x, b0.y, b0.z, b0.w, b1.x, b1.y, b1.z, b1.w};
            #pragma unroll
            for (int r = 0; r < 8; ++r)
                #pragma unroll
                for (int c = 0; c < 8; ++c)
                    acc[r][c] = fmaf(ra[r], rb[c], acc[r][c]);
        }
        if (t < 15) {
            #pragma unroll
            for (int it = 0; it < 2; ++it) {
                int row = lrow0 + it * 64;
                As[nxt][kq+0][row] = pa[it].x; As[nxt][kq+1][row] = pa[it].y;
                As[nxt][kq+2][row] = pa[it].z; As[nxt][kq+3][row] = pa[it].w;
                Bs[nxt][kq+0][row] = pb[it].x; Bs[nxt][kq+1][row] = pb[it].y;
                Bs[nxt][kq+2][row] = pb[it].z; Bs[nxt][kq+3][row] = pb[it].w;
            }
            __syncthreads();
        }
    }

    // --- epilogue: L2 -> kernel value via a + a^2 + a^4 + a^8 + a^16 ----
    int rowbase = bi * TILE + ty * 8;
    int colbase = bj * TILE + tx * 8;
    float rsq[8], csq[8];
    #pragma unroll
    for (int r = 0; r < 8; ++r) rsq[r] = g_sq[rowbase + r];
    #pragma unroll
    for (int c = 0; c < 8; ++c) csq[c] = g_sq[colbase + c];
    float ce = g_cexp;

    float tsum = 0.f;
    #pragma unroll
    for (int r = 0; r < 8; ++r) {
        #pragma unroll
        for (int c = 0; c < 8; ++c) {
            float L2 = fmaf(-2.f, acc[r][c], rsq[r] + csq[c]);
            L2 = fmaxf(L2, 0.f);
            float a;
            asm("ex2.approx.f32 %0, %1;" : "=f"(a) : "f"(-ce * L2));
            float a2 = a * a, a4 = a2 * a2, a8 = a4 * a4, a16 = a8 * a8;
            tsum += ((a + a2) + (a4 + a8)) + a16;
        }
    }
    #pragma unroll
    for (int o = 16; o; o >>= 1) tsum += __shfl_xor_sync(0xffffffffu, tsum, o);
    if (lane == 0) wred[warp] = tsum;
    __syncthreads();
    if (tid == 0) {
        double bs = 0.0;
        #pragma unroll
        for (int w = 0; w < 8; ++w) bs += (double)wred[w];
        double wgt = (bi == bj) ? 1.0 : 2.0;
        double sgn = ((bi < 32) == (bj < 32)) ? 1.0 : -1.0;
        atomicAdd(&g_acc, bs * wgt * sgn);
    }
}

// ---------------------------------------------------------------- finalize
__global__ void k_final(float* out) {
    if (threadIdx.x == 0 && blockIdx.x == 0)
        out[0] = (float)(g_acc / ((double)NS * (double)NS));
}

// ---------------------------------------------------------------- launch
extern "C" void kernel_launch(void* const* d_in, const int* in_sizes, int n_in,
                              void* d_out, int out_size) {
    const float* src = (const float*)d_in[0];
    const float* tgt = (const float*)d_in[1];
    float* out = (float*)d_out;

    k_zero <<<1, 256>>>();
    k_stats<<<64, 256>>>(src, tgt);
    k_prep <<<1, 256>>>();
    k_mmd  <<<NPAIRS, 256>>>(src, tgt);
    k_final<<<1, 1>>>(out);
}

// round 5
// speedup vs baseline: 3.9173x; 3.9173x over previous
#include <cuda_runtime.h>
#include <cuda_fp16.h>
#include <math.h>
#include <stdint.h>

#define D      256
#define NS     4096
#define NTOT   8192
#define TILE   128
#define TBLK   64
#define NPAIRS (TBLK*(TBLK+1)/2)        // 2080

// ---------------- device state / scratch ----------------
__device__ float  g_sq[NTOT];
__device__ float  g_colsum[D];
__device__ double g_sumsq;
__device__ double g_acc;
__device__ float  g_cexp;
__device__ __align__(16) __half g_hi[NTOT * D];
__device__ __align__(16) __half g_lo[NTOT * D];

// ---------------- helpers ----------------
__device__ __forceinline__ uint32_t smem_u32(const void* p) {
    uint32_t a;
    asm("{ .reg .u64 t; cvta.to.shared.u64 t, %1; cvt.u32.u64 %0, t; }" : "=r"(a) : "l"(p));
    return a;
}
__device__ __forceinline__ uint32_t swz(uint32_t off) {      // SW128 swizzle
    return off ^ ((off >> 3) & 0x70);
}
__device__ __forceinline__ void ldsm4(uint32_t* r, uint32_t addr) {
    asm volatile("ldmatrix.sync.aligned.m8n8.x4.shared.b16 {%0,%1,%2,%3}, [%4];"
                 : "=r"(r[0]), "=r"(r[1]), "=r"(r[2]), "=r"(r[3]) : "r"(addr));
}
__device__ __forceinline__ void mma16816(float* c, const uint32_t* a,
                                         uint32_t b0, uint32_t b1) {
    asm volatile(
        "mma.sync.aligned.m16n8k16.row.col.f32.f16.f16.f32 "
        "{%0,%1,%2,%3}, {%4,%5,%6,%7}, {%8,%9}, {%0,%1,%2,%3};"
        : "+f"(c[0]), "+f"(c[1]), "+f"(c[2]), "+f"(c[3])
        : "r"(a[0]), "r"(a[1]), "r"(a[2]), "r"(a[3]), "r"(b0), "r"(b1));
}

// ---------------- zero state ----------------
__global__ void k_zero() {
    int t = threadIdx.x;
    if (t < D) g_colsum[t] = 0.f;
    if (t == 0) { g_sumsq = 0.0; g_acc = 0.0; }
}

// ---------------- row stats ----------------
__global__ void k_stats(const float* __restrict__ src, const float* __restrict__ tgt) {
    int b = blockIdx.x, tid = threadIdx.x, lane = tid & 31, warp = tid >> 5;
    __shared__ float wsum[8];

    float ssq_local = 0.f;
    for (int r = warp; r < TILE; r += 8) {
        int i = b * TILE + r;
        const float* row = (i < NS) ? src + (size_t)i * D : tgt + (size_t)(i - NS) * D;
        float4 v0 = ((const float4*)row)[lane * 2];
        float4 v1 = ((const float4*)row)[lane * 2 + 1];
        float s = v0.x*v0.x + v0.y*v0.y + v0.z*v0.z + v0.w*v0.w
                + v1.x*v1.x + v1.y*v1.y + v1.z*v1.z + v1.w*v1.w;
        #pragma unroll
        for (int o = 16; o; o >>= 1) s += __shfl_xor_sync(0xffffffffu, s, o);
        if (lane == 0) { g_sq[i] = s; ssq_local += s; }
    }
    if (lane == 0) wsum[warp] = ssq_local;
    __syncthreads();
    if (tid == 0) {
        double bs = 0.0;
        #pragma unroll
        for (int w = 0; w < 8; ++w) bs += (double)wsum[w];
        atomicAdd(&g_sumsq, bs);
    }

    float cs = 0.f;
    for (int r = 0; r < TILE; ++r) {
        int i = b * TILE + r;
        const float* row = (i < NS) ? src + (size_t)i * D : tgt + (size_t)(i - NS) * D;
        cs += row[tid];
    }
    atomicAdd(&g_colsum[tid], cs);
}

// ---------------- bandwidth (closed form, fp64) ----------------
__global__ void k_prep() {
    __shared__ double sh[256];
    float c = g_colsum[threadIdx.x];
    sh[threadIdx.x] = (double)c * (double)c;
    __syncthreads();
    for (int o = 128; o; o >>= 1) {
        if (threadIdx.x < o) sh[threadIdx.x] += sh[threadIdx.x + o];
        __syncthreads();
    }
    if (threadIdx.x == 0) {
        double n     = (double)NTOT;
        double sumL2 = 2.0 * n * g_sumsq - 2.0 * sh[0];
        double bw0   = sumL2 / (n * n - n) / 4.0;
        g_cexp = (float)(1.4426950408889634 / (bw0 * 16.0));  // a = 2^(-cexp*L2)
    }
}

// ---------------- hi/lo fp16 split ----------------
__global__ void k_split(const float* __restrict__ src, const float* __restrict__ tgt) {
    int idx = blockIdx.x * blockDim.x + threadIdx.x;          // one float4
    const int NSV = NS * D / 4;
    float4 v = (idx < NSV) ? ((const float4*)src)[idx] : ((const float4*)tgt)[idx - NSV];
    float vv[4] = {v.x, v.y, v.z, v.w};
    __half h[4], l[4];
    #pragma unroll
    for (int i = 0; i < 4; ++i) {
        h[i] = __float2half(vv[i]);
        l[i] = __float2half(vv[i] - __half2float(h[i]));
    }
    int base = idx * 4;
    *(uint2*)&g_hi[base] = *(uint2*)h;
    *(uint2*)&g_lo[base] = *(uint2*)l;
}

// ---------------- kernel value: a + a^2 + a^4 + a^8 + a^16 ----------------
__device__ __forceinline__ float kernel_sum(float dot, float sq, float ce) {
    float L2 = fmaxf(fmaf(-2.f, dot, sq), 0.f);
    float a;
    asm("ex2.approx.f32 %0, %1;" : "=f"(a) : "f"(-ce * L2));
    float a2 = a * a, a4 = a2 * a2, a8 = a4 * a4, a16 = a8 * a8;
    return ((a + a2) + (a4 + a8)) + a16;
}

// ---------------- main: HMMA Gram tiles ----------------
// smem: [0..512) csq(128f), [512..544) wred, tiles @1024: Ahi,Alo,Bhi,Blo
// each tile: 128 rows x 64 fp16 = 128B/row, SW128-swizzled, 16KB
#define T_AHI 1024
#define T_ALO (1024 + 16384)
#define T_BHI (1024 + 32768)
#define T_BLO (1024 + 49152)
#define SM_BYTES (1024 + 4 * 16384)

__device__ __forceinline__ void load_tile(char* sdst, const __half* g, int tid) {
    #pragma unroll
    for (int i = 0; i < 4; ++i) {
        int e = tid + i * 256;
        int row = e >> 3, q = e & 7;
        uint4 v = *(const uint4*)((const char*)g + (size_t)row * (D * 2) + q * 16);
        *(uint4*)(sdst + swz(row * 128 + q * 16)) = v;
    }
}

__global__ void __launch_bounds__(256, 2) k_mmd() {
    extern __shared__ char smem[];
    uint32_t sb = smem_u32(smem);
    int tid = threadIdx.x, wid = tid >> 5, lane = tid & 31;

    // ---- linear pair index -> (bi, bj), bi <= bj ----
    int idx = blockIdx.x;
    float tt = 2.f * TBLK + 1.f;
    int bi = (int)((tt - sqrtf(tt * tt - 8.f * (float)idx)) * 0.5f);
    if (bi < 0) bi = 0;
    if (bi > TBLK - 1) bi = TBLK - 1;
    while (bi > 0 && bi * TBLK - bi * (bi - 1) / 2 > idx) --bi;
    while ((bi + 1) * TBLK - (bi + 1) * bi / 2 <= idx) ++bi;
    int bj = bi + idx - (bi * TBLK - bi * (bi - 1) / 2);

    const __half* Ahi = g_hi + (size_t)bi * TILE * D;
    const __half* Alo = g_lo + (size_t)bi * TILE * D;
    const __half* Bhi = g_hi + (size_t)bj * TILE * D;
    const __half* Blo = g_lo + (size_t)bj * TILE * D;

    if (tid < 128) ((float*)smem)[tid] = g_sq[bj * TILE + tid];

    // ---- warp tiling: 4 warps along M (32 each), 2 along N (64 each) ----
    int warp_m = wid & 3, warp_n = wid >> 2;
    int lane7 = lane & 7;
    int aRowOff = ((lane >> 3) & 1) * 8, aKoff = ((lane >> 4) & 1) * 8;
    int bNoff   = ((lane >> 4) & 1) * 8, bKoff = ((lane >> 3) & 1) * 8;

    uint32_t rowA[2], rowB[4];
    #pragma unroll
    for (int f = 0; f < 2; ++f)
        rowA[f] = (warp_m * 32 + f * 16 + aRowOff + lane7) * 128;
    #pragma unroll
    for (int q = 0; q < 4; ++q)
        rowB[q] = (warp_n * 64 + q * 16 + bNoff + lane7) * 128;

    float C[2][8][4];
    #pragma unroll
    for (int f = 0; f < 2; ++f)
        #pragma unroll
        for (int g = 0; g < 8; ++g)
            #pragma unroll
            for (int r = 0; r < 4; ++r) C[f][g][r] = 0.f;

    for (int c = 0; c < 4; ++c) {
        load_tile(smem + T_AHI, Ahi + c * 64, tid);
        load_tile(smem + T_ALO, Alo + c * 64, tid);
        load_tile(smem + T_BHI, Bhi + c * 64, tid);
        load_tile(smem + T_BLO, Blo + c * 64, tid);
        __syncthreads();

        #pragma unroll
        for (int ks = 0; ks < 4; ++ks) {
            uint32_t kbA = (ks * 16 + aKoff) * 2;
            uint32_t kbB = (ks * 16 + bKoff) * 2;
            uint32_t aH[2][4], aL[2][4], b[4][4];
            #pragma unroll
            for (int f = 0; f < 2; ++f) {
                ldsm4(aH[f], sb + T_AHI + swz(rowA[f] + kbA));
                ldsm4(aL[f], sb + T_ALO + swz(rowA[f] + kbA));
            }
            // pass 1+2: (hi,lo of A) x hi of B
            #pragma unroll
            for (int q = 0; q < 4; ++q) ldsm4(b[q], sb + T_BHI + swz(rowB[q] + kbB));
            #pragma unroll
            for (int f = 0; f < 2; ++f)
                #pragma unroll
                for (int q = 0; q < 4; ++q) {
                    mma16816(C[f][2*q],   aH[f], b[q][0], b[q][1]);
                    mma16816(C[f][2*q+1], aH[f], b[q][2], b[q][3]);
                    mma16816(C[f][2*q],   aL[f], b[q][0], b[q][1]);
                    mma16816(C[f][2*q+1], aL[f], b[q][2], b[q][3]);
                }
            // pass 3: hi of A x lo of B
            #pragma unroll
            for (int q = 0; q < 4; ++q) ldsm4(b[q], sb + T_BLO + swz(rowB[q] + kbB));
            #pragma unroll
            for (int f = 0; f < 2; ++f)
                #pragma unroll
                for (int q = 0; q < 4; ++q) {
                    mma16816(C[f][2*q],   aH[f], b[q][0], b[q][1]);
                    mma16816(C[f][2*q+1], aH[f], b[q][2], b[q][3]);
                }
        }
        __syncthreads();
    }

    // ---- epilogue ----
    int lr = lane >> 2, lc = (lane & 3) * 2;
    float rsqv[2][2];
    #pragma unroll
    for (int f = 0; f < 2; ++f)
        #pragma unroll
        for (int h = 0; h < 2; ++h)
            rsqv[f][h] = g_sq[bi * TILE + warp_m * 32 + f * 16 + h * 8 + lr];
    float ccv[16];
    const float* csq = (const float*)smem;
    #pragma unroll
    for (int g = 0; g < 8; ++g) {
        ccv[g * 2]     = csq[warp_n * 64 + g * 8 + lc];
        ccv[g * 2 + 1] = csq[warp_n * 64 + g * 8 + lc + 1];
    }
    float ce = g_cexp;

    float tsum = 0.f;
    #pragma unroll
    for (int f = 0; f < 2; ++f)
        #pragma unroll
        for (int g = 0; g < 8; ++g)
            #pragma unroll
            for (int r = 0; r < 4; ++r)
                tsum += kernel_sum(C[f][g][r], rsqv[f][r >> 1] + ccv[g * 2 + (r & 1)], ce);

    #pragma unroll
    for (int o = 16; o; o >>= 1) tsum += __shfl_xor_sync(0xffffffffu, tsum, o);
    if (lane == 0) ((float*)(smem + 512))[wid] = tsum;
    __syncthreads();

    if (tid == 0) {
        const float* wr = (const float*)(smem + 512);
        double bs = 0.0;
        #pragma unroll
        for (int w = 0; w < 8; ++w) bs += (double)wr[w];
        double wgt = (bi == bj) ? 1.0 : 2.0;
        double sgn = ((bi < 32) == (bj < 32)) ? 1.0 : -1.0;
        atomicAdd(&g_acc, bs * wgt * sgn);
    }
}

// ---------------- finalize ----------------
__global__ void k_final(float* out) {
    if (threadIdx.x == 0 && blockIdx.x == 0)
        out[0] = (float)(g_acc / ((double)NS * (double)NS));
}

// ---------------- launch ----------------
extern "C" void kernel_launch(void* const* d_in, const int* in_sizes, int n_in,
                              void* d_out, int out_size) {
    const float* src = (const float*)d_in[0];
    const float* tgt = (const float*)d_in[1];
    float* out = (float*)d_out;

    cudaFuncSetAttribute(k_mmd, cudaFuncAttributeMaxDynamicSharedMemorySize, SM_BYTES);

    k_zero <<<1, 256>>>();
    k_stats<<<64, 256>>>(src, tgt);
    k_prep <<<1, 256>>>();
    k_split<<<(NTOT * D / 4) / 256, 256>>>(src, tgt);
    k_mmd  <<<NPAIRS, 256, SM_BYTES>>>();
    k_final<<<1, 1>>>(out);
}

// round 6
// speedup vs baseline: 8.2256x; 2.0998x over previous
#include <cuda_runtime.h>
#include <cuda_fp16.h>
#include <math.h>
#include <stdint.h>

#define D      256
#define NS     4096
#define NTOT   8192
#define TILE   128
#define TBLK   64
#define NPAIRS (TBLK*(TBLK+1)/2)        // 2080

// ---------------- device state / scratch ----------------
__device__ float  g_sq[NTOT];           // row norms of ROUNDED data
__device__ float  g_colsum[D];
__device__ double g_sumsq;              // exact sum of squares (for bw0)
__device__ double g_acc;
__device__ float  g_cexp;
__device__ __align__(16) __half g_hi[NTOT * D];

// ---------------- helpers ----------------
__device__ __forceinline__ uint32_t smem_u32(const void* p) {
    uint32_t a;
    asm("{ .reg .u64 t; cvta.to.shared.u64 t, %1; cvt.u32.u64 %0, t; }" : "=r"(a) : "l"(p));
    return a;
}
__device__ __forceinline__ uint32_t swz(uint32_t off) {      // SW128 swizzle
    return off ^ ((off >> 3) & 0x70);
}
__device__ __forceinline__ void ldsm4(uint32_t* r, uint32_t addr) {
    asm volatile("ldmatrix.sync.aligned.m8n8.x4.shared.b16 {%0,%1,%2,%3}, [%4];"
                 : "=r"(r[0]), "=r"(r[1]), "=r"(r[2]), "=r"(r[3]) : "r"(addr));
}
__device__ __forceinline__ void mma16816(float* c, const uint32_t* a,
                                         uint32_t b0, uint32_t b1) {
    asm volatile(
        "mma.sync.aligned.m16n8k16.row.col.f32.f16.f16.f32 "
        "{%0,%1,%2,%3}, {%4,%5,%6,%7}, {%8,%9}, {%0,%1,%2,%3};"
        : "+f"(c[0]), "+f"(c[1]), "+f"(c[2]), "+f"(c[3])
        : "r"(a[0]), "r"(a[1]), "r"(a[2]), "r"(a[3]), "r"(b0), "r"(b1));
}
__device__ __forceinline__ void cpasync16(uint32_t dst, const void* src) {
    asm volatile("cp.async.cg.shared.global [%0], [%1], 16;" :: "r"(dst), "l"(src));
}

// ---------------- zero state ----------------
__global__ void k_zero() {
    int t = threadIdx.x;
    if (t < D) g_colsum[t] = 0.f;
    if (t == 0) { g_sumsq = 0.0; g_acc = 0.0; }
}

// ---------------- fused stats + fp16 convert ----------------
// 64 blocks x 256 threads; block b owns rows [b*128, b*128+128)
__global__ void k_stats(const float* __restrict__ src, const float* __restrict__ tgt) {
    int b = blockIdx.x, tid = threadIdx.x, lane = tid & 31, warp = tid >> 5;
    __shared__ float wsum[8];

    float ssq_local = 0.f;
    for (int r = warp; r < TILE; r += 8) {
        int i = b * TILE + r;
        const float* row = (i < NS) ? src + (size_t)i * D : tgt + (size_t)(i - NS) * D;
        float4 v0 = ((const float4*)row)[lane * 2];
        float4 v1 = ((const float4*)row)[lane * 2 + 1];
        float vv[8] = {v0.x, v0.y, v0.z, v0.w, v1.x, v1.y, v1.z, v1.w};
        __half h[8];
        float s_ex = 0.f, s_hi = 0.f;
        #pragma unroll
        for (int e = 0; e < 8; ++e) {
            h[e] = __float2half(vv[e]);
            float hf = __half2float(h[e]);
            s_ex += vv[e] * vv[e];
            s_hi += hf * hf;
        }
        *(uint4*)&g_hi[(size_t)i * D + lane * 8] = *(uint4*)h;
        #pragma unroll
        for (int o = 16; o; o >>= 1) {
            s_ex += __shfl_xor_sync(0xffffffffu, s_ex, o);
            s_hi += __shfl_xor_sync(0xffffffffu, s_hi, o);
        }
        if (lane == 0) { g_sq[i] = s_hi; ssq_local += s_ex; }
    }
    if (lane == 0) wsum[warp] = ssq_local;
    __syncthreads();
    if (tid == 0) {
        double bs = 0.0;
        #pragma unroll
        for (int w = 0; w < 8; ++w) bs += (double)wsum[w];
        atomicAdd(&g_sumsq, bs);
    }

    float cs = 0.f;
    for (int r = 0; r < TILE; ++r) {
        int i = b * TILE + r;
        const float* row = (i < NS) ? src + (size_t)i * D : tgt + (size_t)(i - NS) * D;
        cs += row[tid];
    }
    atomicAdd(&g_colsum[tid], cs);
}

// ---------------- bandwidth (closed form, fp64, exact data) ----------------
__global__ void k_prep() {
    __shared__ double sh[256];
    float c = g_colsum[threadIdx.x];
    sh[threadIdx.x] = (double)c * (double)c;
    __syncthreads();
    for (int o = 128; o; o >>= 1) {
        if (threadIdx.x < o) sh[threadIdx.x] += sh[threadIdx.x + o];
        __syncthreads();
    }
    if (threadIdx.x == 0) {
        double n     = (double)NTOT;
        double sumL2 = 2.0 * n * g_sumsq - 2.0 * sh[0];
        double bw0   = sumL2 / (n * n - n) / 4.0;
        g_cexp = (float)(1.4426950408889634 / (bw0 * 16.0));  // a = 2^(-cexp*L2)
    }
}

// ---------------- kernel value: a + a^2 + a^4 + a^8 + a^16 ----------------
__device__ __forceinline__ float kernel_sum(float dot, float sq, float ce) {
    float L2 = fmaxf(fmaf(-2.f, dot, sq), 0.f);
    float a;
    asm("ex2.approx.f32 %0, %1;" : "=f"(a) : "f"(-ce * L2));
    float a2 = a * a, a4 = a2 * a2, a8 = a4 * a4, a16 = a8 * a8;
    return ((a + a2) + (a4 + a8)) + a16;
}

// ---------------- main: single-pass HMMA Gram tiles, cp.async 2-stage ----
// smem: [0..512) csq(128f), [512..544) wred,
// buffers @1024: buf s in {0,1}: A @ 1024+s*32768, B @ +16384
// tile = 128 rows x 64 fp16 = 128B/row, SW128-swizzled, 16KB
#define SM_BUF   1024
#define SM_BYTES (1024 + 4 * 16384)

__global__ void __launch_bounds__(256, 2) k_mmd() {
    extern __shared__ char smem[];
    uint32_t sb = smem_u32(smem);
    int tid = threadIdx.x, wid = tid >> 5, lane = tid & 31;

    // ---- linear pair index -> (bi, bj), bi <= bj ----
    int idx = blockIdx.x;
    float tt = 2.f * TBLK + 1.f;
    int bi = (int)((tt - sqrtf(tt * tt - 8.f * (float)idx)) * 0.5f);
    if (bi < 0) bi = 0;
    if (bi > TBLK - 1) bi = TBLK - 1;
    while (bi > 0 && bi * TBLK - bi * (bi - 1) / 2 > idx) --bi;
    while ((bi + 1) * TBLK - (bi + 1) * bi / 2 <= idx) ++bi;
    int bj = bi + idx - (bi * TBLK - bi * (bi - 1) / 2);

    const __half* A = g_hi + (size_t)bi * TILE * D;
    const __half* B = g_hi + (size_t)bj * TILE * D;

    // per-thread load mapping (4 x 16B per tile)
    int erow[4], eq[4];
    #pragma unroll
    for (int i = 0; i < 4; ++i) { int e = tid + i * 256; erow[i] = e >> 3; eq[i] = e & 7; }

    // issue chunk c into buffer c&1
    auto issue = [&](int c) {
        uint32_t ab = sb + SM_BUF + (c & 1) * 32768;
        uint32_t bb = ab + 16384;
        const char* As = (const char*)(A + c * 64);
        const char* Bs = (const char*)(B + c * 64);
        #pragma unroll
        for (int i = 0; i < 4; ++i) {
            uint32_t off = swz(erow[i] * 128 + eq[i] * 16);
            size_t go = (size_t)erow[i] * 512 + eq[i] * 16;
            cpasync16(ab + off, As + go);
            cpasync16(bb + off, Bs + go);
        }
        asm volatile("cp.async.commit_group;" ::: "memory");
    };
    issue(0);

    if (tid < 128) ((float*)smem)[tid] = g_sq[bj * TILE + tid];

    // ---- warp tiling: 4 warps along M (32 each), 2 along N (64 each) ----
    int warp_m = wid & 3, warp_n = wid >> 2;
    int lane7 = lane & 7;
    int aRowOff = ((lane >> 3) & 1) * 8, aKoff = ((lane >> 4) & 1) * 8;
    int bNoff   = ((lane >> 4) & 1) * 8, bKoff = ((lane >> 3) & 1) * 8;

    uint32_t rowA[2], rowB[4];
    #pragma unroll
    for (int f = 0; f < 2; ++f)
        rowA[f] = (warp_m * 32 + f * 16 + aRowOff + lane7) * 128;
    #pragma unroll
    for (int q = 0; q < 4; ++q)
        rowB[q] = (warp_n * 64 + q * 16 + bNoff + lane7) * 128;

    float C[2][8][4];
    #pragma unroll
    for (int f = 0; f < 2; ++f)
        #pragma unroll
        for (int g = 0; g < 8; ++g)
            #pragma unroll
            for (int r = 0; r < 4; ++r) C[f][g][r] = 0.f;

    for (int c = 0; c < 4; ++c) {
        asm volatile("cp.async.wait_group 0;" ::: "memory");
        __syncthreads();
        if (c < 3) issue(c + 1);

        uint32_t ab = sb + SM_BUF + (c & 1) * 32768;
        uint32_t bb = ab + 16384;
        #pragma unroll
        for (int ks = 0; ks < 4; ++ks) {
            uint32_t kbA = (ks * 16 + aKoff) * 2;
            uint32_t kbB = (ks * 16 + bKoff) * 2;
            uint32_t aH[2][4], b[4][4];
            #pragma unroll
            for (int f = 0; f < 2; ++f) ldsm4(aH[f], ab + swz(rowA[f] + kbA));
            #pragma unroll
            for (int q = 0; q < 4; ++q) ldsm4(b[q], bb + swz(rowB[q] + kbB));
            #pragma unroll
            for (int f = 0; f < 2; ++f)
                #pragma unroll
                for (int q = 0; q < 4; ++q) {
                    mma16816(C[f][2*q],   aH[f], b[q][0], b[q][1]);
                    mma16816(C[f][2*q+1], aH[f], b[q][2], b[q][3]);
                }
        }
    }

    // ---- epilogue ----
    int lr = lane >> 2, lc = (lane & 3) * 2;
    float rsqv[2][2];
    #pragma unroll
    for (int f = 0; f < 2; ++f)
        #pragma unroll
        for (int h = 0; h < 2; ++h)
            rsqv[f][h] = g_sq[bi * TILE + warp_m * 32 + f * 16 + h * 8 + lr];
    float ccv[16];
    const float* csq = (const float*)smem;
    #pragma unroll
    for (int g = 0; g < 8; ++g) {
        ccv[g * 2]     = csq[warp_n * 64 + g * 8 + lc];
        ccv[g * 2 + 1] = csq[warp_n * 64 + g * 8 + lc + 1];
    }
    float ce = g_cexp;

    float tsum = 0.f;
    #pragma unroll
    for (int f = 0; f < 2; ++f)
        #pragma unroll
        for (int g = 0; g < 8; ++g)
            #pragma unroll
            for (int r = 0; r < 4; ++r)
                tsum += kernel_sum(C[f][g][r], rsqv[f][r >> 1] + ccv[g * 2 + (r & 1)], ce);

    #pragma unroll
    for (int o = 16; o; o >>= 1) tsum += __shfl_xor_sync(0xffffffffu, tsum, o);
    if (lane == 0) ((float*)(smem + 512))[wid] = tsum;
    __syncthreads();

    if (tid == 0) {
        const float* wr = (const float*)(smem + 512);
        double bs = 0.0;
        #pragma unroll
        for (int w = 0; w < 8; ++w) bs += (double)wr[w];
        double wgt = (bi == bj) ? 1.0 : 2.0;
        double sgn = ((bi < 32) == (bj < 32)) ? 1.0 : -1.0;
        atomicAdd(&g_acc, bs * wgt * sgn);
    }
}

// ---------------- finalize ----------------
__global__ void k_final(float* out) {
    if (threadIdx.x == 0 && blockIdx.x == 0)
        out[0] = (float)(g_acc / ((double)NS * (double)NS));
}

// ---------------- launch ----------------
extern "C" void kernel_launch(void* const* d_in, const int* in_sizes, int n_in,
                              void* d_out, int out_size) {
    const float* src = (const float*)d_in[0];
    const float* tgt = (const float*)d_in[1];
    float* out = (float*)d_out;

    cudaFuncSetAttribute(k_mmd, cudaFuncAttributeMaxDynamicSharedMemorySize, SM_BYTES);

    k_zero <<<1, 256>>>();
    k_stats<<<64, 256>>>(src, tgt);
    k_prep <<<1, 256>>>();
    k_mmd  <<<NPAIRS, 256, SM_BYTES>>>();
    k_final<<<1, 1>>>(out);
}